// round 9
// baseline (speedup 1.0000x reference)
#include <cuda_runtime.h>
#include <cuda_bf16.h>

// T=50, H=W=8, NH=16, B=8, TP=TF=8, HIDDEN=512, RPE_COEF=16
#define NROW   22275          // 99*15*15
#define NROWP  22400          // 175 * 128 (block coverage)
#define NHEAD  16
#define HIDDEN 512

// Scratch: g_rpt[nh][row] = 16*sigmoid( (relu(rct@W1+b1)@W2)[row][nh] )
__device__ float g_rpt[NHEAD * NROWP];

typedef unsigned long long u64;

// ---- packed f32x2 helpers (Blackwell) --------------------------------------
__device__ __forceinline__ u64 pk64(float lo, float hi) {
    u64 r; asm("mov.b64 %0, {%1, %2};" : "=l"(r) : "f"(lo), "f"(hi)); return r;
}
__device__ __forceinline__ void upk64(u64 v, float& lo, float& hi) {
    asm("mov.b64 {%0, %1}, %2;" : "=f"(lo), "=f"(hi) : "l"(v));
}
__device__ __forceinline__ u64 fma2(u64 a, u64 b, u64 c) {
    u64 d; asm("fma.rn.f32x2 %0, %1, %2, %3;" : "=l"(d) : "l"(a), "l"(b), "l"(c)); return d;
}
__device__ __forceinline__ u64 add2(u64 a, u64 b) {
    u64 d; asm("add.rn.f32x2 %0, %1, %2;" : "=l"(d) : "l"(a), "l"(b)); return d;
}

// ---------------------------------------------------------------------------
// Kernel 1: FUSED cpb MLP, single phase, no smem reduction.
//  Block 256 thr = 32 row-groups x 8 h-slices.  thread: s = tid&7 (64-h slice,
//  slice-interleaved smem so LDS stays conflict-free), rg = tid>>3 (4 rows).
//  Per h: 1 LDS.128 (W1|b1) + 4 LDS.128 (W2 as packed ulonglong2 -> no MOVs)
//         + 12 FMA + 4 relu (hidden) + 4 pack + 32 fma.rn.f32x2.
//  Reduction over the 8 slices: 3-round shfl.xor butterfly on f32x2 lanes.
// ---------------------------------------------------------------------------
__global__ void __launch_bounds__(256, 2) mlp_kernel(
    const float* __restrict__ rct,   // [NROW, 3]
    const float* __restrict__ W1,    // [3, 512]
    const float* __restrict__ b1,    // [512]
    const float* __restrict__ W2)    // [512, 16]
{
    // slot = i*8 + s  <->  h = s*64 + i
    __shared__ float4     sW14s[512];        // 8 KB  : {W1_0,W1_1,W1_2,b1}[h]
    __shared__ ulonglong2 sW2s[512 * 5];     // 40 KB : pad-5 -> conflict-free

    const int tid  = threadIdx.x;
    const int s    = tid & 7;
    const int rg   = tid >> 3;               // 0..31
    const int row0 = blockIdx.x * 128;

    // Stage weights (interleaved layouts)
    #pragma unroll
    for (int d = tid; d < 512; d += 256) {
        const int h = (d & 7) * 64 + (d >> 3);
        sW14s[d] = make_float4(__ldg(W1 + h), __ldg(W1 + HIDDEN + h),
                               __ldg(W1 + 2 * HIDDEN + h), __ldg(b1 + h));
    }
    {
        const ulonglong2* __restrict__ w2v = reinterpret_cast<const ulonglong2*>(W2);
        #pragma unroll
        for (int d = tid; d < 2048; d += 256) {
            const int slot = d >> 2, q = d & 3;
            const int h = (slot & 7) * 64 + (slot >> 3);
            sW2s[slot * 5 + q] = __ldg(w2v + h * 4 + q);
        }
    }

    // Coordinates for 4 rows (12 consecutive floats = 3 float4, guarded at tail)
    const int rbase = row0 + rg * 4;
    float c0[4], c1[4], c2[4];
    if (rbase + 3 < NROW) {
        const float4 f0 = __ldg((const float4*)(rct + rbase * 3));
        const float4 f1 = __ldg((const float4*)(rct + rbase * 3) + 1);
        const float4 f2 = __ldg((const float4*)(rct + rbase * 3) + 2);
        c0[0]=f0.x; c1[0]=f0.y; c2[0]=f0.z;
        c0[1]=f0.w; c1[1]=f1.x; c2[1]=f1.y;
        c0[2]=f1.z; c1[2]=f1.w; c2[2]=f2.x;
        c0[3]=f2.y; c1[3]=f2.z; c2[3]=f2.w;
    } else {
        #pragma unroll
        for (int j = 0; j < 4; j++) {
            const int r = rbase + j;
            if (r < NROW) { c0[j]=__ldg(rct+r*3); c1[j]=__ldg(rct+r*3+1); c2[j]=__ldg(rct+r*3+2); }
            else          { c0[j]=c1[j]=c2[j]=0.f; }
        }
    }
    __syncthreads();

    // Main loop: 64 h per slice. acc[j*8+p] : row j, nh pair p (nh = 2p, 2p+1)
    u64 acc[32];
    #pragma unroll
    for (int k = 0; k < 32; k++) acc[k] = 0ull;

    #pragma unroll 4
    for (int i = 0; i < 64; i++) {
        const int slot = i * 8 + s;
        const float4 wc = sW14s[slot];
        u64 hh[4];
        #pragma unroll
        for (int j = 0; j < 4; j++) {
            const float hv = fmaxf(
                fmaf(c2[j], wc.z, fmaf(c1[j], wc.y, fmaf(c0[j], wc.x, wc.w))), 0.f);
            hh[j] = pk64(hv, hv);
        }
        const ulonglong2 wA = sW2s[slot * 5 + 0];
        const ulonglong2 wB = sW2s[slot * 5 + 1];
        const ulonglong2 wC = sW2s[slot * 5 + 2];
        const ulonglong2 wD = sW2s[slot * 5 + 3];
        #pragma unroll
        for (int j = 0; j < 4; j++) {
            acc[j*8+0] = fma2(hh[j], wA.x, acc[j*8+0]);
            acc[j*8+1] = fma2(hh[j], wA.y, acc[j*8+1]);
            acc[j*8+2] = fma2(hh[j], wB.x, acc[j*8+2]);
            acc[j*8+3] = fma2(hh[j], wB.y, acc[j*8+3]);
            acc[j*8+4] = fma2(hh[j], wC.x, acc[j*8+4]);
            acc[j*8+5] = fma2(hh[j], wC.y, acc[j*8+5]);
            acc[j*8+6] = fma2(hh[j], wD.x, acc[j*8+6]);
            acc[j*8+7] = fma2(hh[j], wD.y, acc[j*8+7]);
        }
    }

    // Butterfly reduction over slices (lane bits 0,1,2). Payload halves per round.
    u64 r1[16];
    {
        const int side = s & 1;              // 0: keep nh 0-7 (p 0-3)
        #pragma unroll
        for (int j = 0; j < 4; j++)
            #pragma unroll
            for (int p = 0; p < 4; p++) {
                const u64 snd = side ? acc[j*8+p]   : acc[j*8+p+4];
                const u64 kp  = side ? acc[j*8+p+4] : acc[j*8+p];
                r1[j*4+p] = add2(kp, __shfl_xor_sync(0xffffffffu, snd, 1));
            }
    }
    u64 r2[8];
    {
        const int side = (s >> 1) & 1;
        #pragma unroll
        for (int j = 0; j < 4; j++)
            #pragma unroll
            for (int p = 0; p < 2; p++) {
                const u64 snd = side ? r1[j*4+p]   : r1[j*4+p+2];
                const u64 kp  = side ? r1[j*4+p+2] : r1[j*4+p];
                r2[j*2+p] = add2(kp, __shfl_xor_sync(0xffffffffu, snd, 2));
            }
    }
    u64 v[4];
    {
        const int side = (s >> 2) & 1;
        #pragma unroll
        for (int j = 0; j < 4; j++) {
            const u64 snd = side ? r2[j*2]   : r2[j*2+1];
            const u64 kp  = side ? r2[j*2+1] : r2[j*2];
            v[j] = add2(kp, __shfl_xor_sync(0xffffffffu, snd, 4));
        }
    }

    // Thread now owns nh pair (nhb, nhb+1) for its 4 rows.
    const int nhb = (s & 1) * 8 + ((s >> 1) & 1) * 4 + ((s >> 2) & 1) * 2;
    float lo[4], hi[4];
    #pragma unroll
    for (int j = 0; j < 4; j++) {
        upk64(v[j], lo[j], hi[j]);
        lo[j] = 16.f / (1.f + __expf(-lo[j]));
        hi[j] = 16.f / (1.f + __expf(-hi[j]));
    }
    *reinterpret_cast<float4*>(g_rpt + nhb * NROWP + rbase) =
        make_float4(lo[0], lo[1], lo[2], lo[3]);
    *reinterpret_cast<float4*>(g_rpt + (nhb + 1) * NROWP + rbase) =
        make_float4(hi[0], hi[1], hi[2], hi[3]);
}

// ---------------------------------------------------------------------------
// Kernel 2: gather. Same structure as R8 but DEFAULT stores (no .cs):
// output (~134 MB) largely fits in the ~126 MB L2, so evict-normal lets the
// kernel run at L2 speed and defers DRAM writeback past kernel end.
//   idx = (t_f + t_p)*225 + (hf-hp+7)*15 + (wf-wp+7)
// ---------------------------------------------------------------------------
__global__ void __launch_bounds__(256) gather_kernel(
    const int* __restrict__ ptc,     // [B, 8] (non-positive; time = -ptc)
    const int* __restrict__ ftc,     // [B, 8]
    float4* __restrict__ out)        // [B, 16, 512, 512] / 4
{
    __shared__ float4 vtab[240];     // [wf][dh+7][par] : wf*30 + dh7*2 + par
    const int tid = threadIdx.x;
    const int blk = blockIdx.x;
    const int tp = blk & 7;
    const int tf = (blk >> 3) & 7;
    const int nh = (blk >> 6) & 15;
    const int b  = blk >> 10;

    const int t_f =  __ldg(ftc + b * 8 + tf);
    const int t_p = -__ldg(ptc + b * 8 + tp);
    const float* __restrict__ src = g_rpt + nh * NROWP + (t_f + t_p) * 225;

    if (tid < 240) {
        const int wf  = tid / 30;
        const int rem = tid - wf * 30;
        const int dh7 = rem >> 1;
        const int par = rem & 1;                       // wp0 = par*4
        const int si  = dh7 * 15 + wf - par * 4 + 7;   // in [3, 224]
        vtab[tid] = make_float4(__ldg(src + si),     __ldg(src + si - 1),
                                __ldg(src + si - 2), __ldg(src + si - 3));
    }
    __syncthreads();

    const int c4    = tid & 15;
    const int fhw0  = tid >> 4;            // 0..15
    const int wf    = fhw0 & 7;
    const int b0    = fhw0 >> 3;           // 0 or 1
    const int hp    = c4 >> 1;
    const int par   = c4 & 1;
    const int base0 = wf * 30 + (b0 - hp + 7) * 2 + par;   // k=0 index

    float4* __restrict__ p =
        out + ((((b * NHEAD + nh) * 512 + tf * 64) * 512 + tp * 64) >> 2)
            + fhw0 * 128 + c4;

    #pragma unroll
    for (int k = 0; k < 4; k++) {
        *p = vtab[base0 + 4 * k];          // hf = b0 + 2k, always <= 7
        p += 2048;                          // fhw += 16
    }
}

// ---------------------------------------------------------------------------
// Launch. Input order: ptc, ftc, W1, b1, W2, rct, rpi_table (unused).
// ---------------------------------------------------------------------------
extern "C" void kernel_launch(void* const* d_in, const int* in_sizes, int n_in,
                              void* d_out, int out_size)
{
    const int*   ptc = (const int*)  d_in[0];
    const int*   ftc = (const int*)  d_in[1];
    const float* W1  = (const float*)d_in[2];
    const float* b1  = (const float*)d_in[3];
    const float* W2  = (const float*)d_in[4];
    const float* rct = (const float*)d_in[5];

    // 175 blocks x 128 rows = 22400 rows (NROWP); rows >= NROW never read.
    mlp_kernel<<<NROWP / 128, 256>>>(rct, W1, b1, W2);

    // 8192 blocks: one per (b, nh, tf, tp) 64x64 tile
    gather_kernel<<<8 * NHEAD * 8 * 8, 256>>>(ptc, ftc, (float4*)d_out);
}

// round 10
// speedup vs baseline: 1.3157x; 1.3157x over previous
#include <cuda_runtime.h>
#include <cuda_bf16.h>

// T=50, H=W=8, NH=16, B=8, TP=TF=8, HIDDEN=512, RPE_COEF=16
#define NROW   22275          // 99*15*15
#define NROWP  22400          // 350 blocks * 64 rows
#define NHEAD  16
#define HIDDEN 512
#define W2TS   520            // bf16 row stride for transposed W2 (conflict-free)

// Scratch: g_rpt[nh][row] = 16*sigmoid( (relu(rct@W1+b1)@W2)[row][nh] )
__device__ float g_rpt[NHEAD * NROWP];

// pack two fp32 -> bf16x2 (lo = first arg)
__device__ __forceinline__ unsigned bfpack(float lo, float hi) {
    unsigned r;
    asm("cvt.rn.bf16x2.f32 %0, %1, %2;" : "=r"(r) : "f"(hi), "f"(lo));
    return r;
}

// ---------------------------------------------------------------------------
// Kernel 1: FUSED cpb MLP with tensor-core layer 2.
//  Block 128 thr = 4 warps; warp w owns rows [row0 + 16w, +16).
//  Per 16-k chunk: lane computes 8 hidden values (fp32, exact A-fragment
//  positions of mma.m16n8k16), packs to bf16x2, loads W2^T b-fragments from
//  padded smem, issues 2 HMMA (nh 0-7 / 8-15) with fp32 accumulation.
//  Epilogue: 16*sigmoid, scatter stores to the transposed table.
// ---------------------------------------------------------------------------
__global__ void __launch_bounds__(128) mlp_kernel(
    const float* __restrict__ rct,   // [NROW, 3]
    const float* __restrict__ W1,    // [3, 512]
    const float* __restrict__ b1,    // [512]
    const float* __restrict__ W2)    // [512, 16]
{
    __shared__ float4 sW14[HIDDEN];                       // 8 KB  {W1_0,W1_1,W1_2,b1}[h]
    __shared__ __align__(16) __nv_bfloat16 sW2T[NHEAD * W2TS];  // 16.25 KB  [n][k]

    const int tid  = threadIdx.x;
    const int wid  = tid >> 5;
    const int lane = tid & 31;
    const int g    = lane >> 2;          // 0..7
    const int t    = lane & 3;           // 0..3
    const int row0 = blockIdx.x * 64;

    // Stage W1|b1
    #pragma unroll
    for (int i = tid; i < HIDDEN; i += 128)
        sW14[i] = make_float4(__ldg(W1 + i), __ldg(W1 + HIDDEN + i),
                              __ldg(W1 + 2 * HIDDEN + i), __ldg(b1 + i));
    // Stage W2 transposed as bf16: sW2T[n][k]
    #pragma unroll
    for (int i = tid; i < HIDDEN * NHEAD; i += 128) {
        const int k = i >> 4, n = i & 15;
        sW2T[n * W2TS + k] = __float2bfloat16(__ldg(W2 + k * NHEAD + n));
    }

    // Coordinates for this lane's two rows (r0 = row, r1 = row + 8)
    const int rw = row0 + wid * 16;
    const int r0 = rw + g, r1 = r0 + 8;
    float cA0 = 0.f, cA1 = 0.f, cA2 = 0.f, cB0 = 0.f, cB1 = 0.f, cB2 = 0.f;
    if (r0 < NROW) { cA0 = __ldg(rct + r0 * 3 + 0);
                     cA1 = __ldg(rct + r0 * 3 + 1);
                     cA2 = __ldg(rct + r0 * 3 + 2); }
    if (r1 < NROW) { cB0 = __ldg(rct + r1 * 3 + 0);
                     cB1 = __ldg(rct + r1 * 3 + 1);
                     cB2 = __ldg(rct + r1 * 3 + 2); }
    __syncthreads();

    float d0[4] = {0.f, 0.f, 0.f, 0.f};   // nh 0-7 tile
    float d1[4] = {0.f, 0.f, 0.f, 0.f};   // nh 8-15 tile

    #pragma unroll 4
    for (int ch = 0; ch < 32; ch++) {
        const int h0 = ch * 16 + 2 * t;   // k positions: h0, h0+1, h0+8, h0+9
        // hidden values at the 4 k-positions for both rows
        float hA[4], hB[4];
        #pragma unroll
        for (int q = 0; q < 4; q++) {
            const int h = h0 + (q & 1) + (q >> 1) * 8;   // h0, h0+1, h0+8, h0+9
            const float4 wc = sW14[h];
            hA[q] = fmaxf(fmaf(cA2, wc.z, fmaf(cA1, wc.y, fmaf(cA0, wc.x, wc.w))), 0.f);
            hB[q] = fmaxf(fmaf(cB2, wc.z, fmaf(cB1, wc.y, fmaf(cB0, wc.x, wc.w))), 0.f);
        }
        const unsigned a0 = bfpack(hA[0], hA[1]);   // row r0, k h0,h0+1
        const unsigned a1 = bfpack(hB[0], hB[1]);   // row r1
        const unsigned a2 = bfpack(hA[2], hA[3]);   // row r0, k h0+8,h0+9
        const unsigned a3 = bfpack(hB[2], hB[3]);   // row r1
        // B fragments: n = g (+8 for tile 1); k pairs (h0,h0+1) and (h0+8,h0+9)
        const unsigned bA0 = *reinterpret_cast<const unsigned*>(&sW2T[g * W2TS + h0]);
        const unsigned bA1 = *reinterpret_cast<const unsigned*>(&sW2T[g * W2TS + h0 + 8]);
        const unsigned bB0 = *reinterpret_cast<const unsigned*>(&sW2T[(g + 8) * W2TS + h0]);
        const unsigned bB1 = *reinterpret_cast<const unsigned*>(&sW2T[(g + 8) * W2TS + h0 + 8]);
        asm volatile(
            "mma.sync.aligned.m16n8k16.row.col.f32.bf16.bf16.f32 "
            "{%0,%1,%2,%3}, {%4,%5,%6,%7}, {%8,%9}, {%0,%1,%2,%3};"
            : "+f"(d0[0]), "+f"(d0[1]), "+f"(d0[2]), "+f"(d0[3])
            : "r"(a0), "r"(a1), "r"(a2), "r"(a3), "r"(bA0), "r"(bA1));
        asm volatile(
            "mma.sync.aligned.m16n8k16.row.col.f32.bf16.bf16.f32 "
            "{%0,%1,%2,%3}, {%4,%5,%6,%7}, {%8,%9}, {%0,%1,%2,%3};"
            : "+f"(d1[0]), "+f"(d1[1]), "+f"(d1[2]), "+f"(d1[3])
            : "r"(a0), "r"(a1), "r"(a2), "r"(a3), "r"(bB0), "r"(bB1));
    }

    // Epilogue: 16*sigmoid + scatter to g_rpt[nh][row].
    // D layout: d[0],d[1] -> row rw+g,  cols 2t, 2t+1 ; d[2],d[3] -> row rw+g+8.
    #pragma unroll
    for (int j = 0; j < 4; j++) {
        d0[j] = 16.f / (1.f + __expf(-d0[j]));
        d1[j] = 16.f / (1.f + __expf(-d1[j]));
    }
    const int nh0 = 2 * t;
    g_rpt[(nh0    ) * NROWP + r0] = d0[0];
    g_rpt[(nh0 + 1) * NROWP + r0] = d0[1];
    g_rpt[(nh0    ) * NROWP + r1] = d0[2];
    g_rpt[(nh0 + 1) * NROWP + r1] = d0[3];
    g_rpt[(nh0 + 8) * NROWP + r0] = d1[0];
    g_rpt[(nh0 + 9) * NROWP + r0] = d1[1];
    g_rpt[(nh0 + 8) * NROWP + r1] = d1[2];
    g_rpt[(nh0 + 9) * NROWP + r1] = d1[3];
}

// ---------------------------------------------------------------------------
// Kernel 2: gather (confirmed at the HBM-write floor; R8 version, __stcs).
// One block per (b, nh, tf, tp) 64x64 tile; vtab holds the 240 distinct
// output float4s; hot loop = 1 LDS.128 + 1 streaming STG.128.
//   idx = (t_f + t_p)*225 + (hf-hp+7)*15 + (wf-wp+7)
// ---------------------------------------------------------------------------
__global__ void __launch_bounds__(256) gather_kernel(
    const int* __restrict__ ptc,     // [B, 8] (non-positive; time = -ptc)
    const int* __restrict__ ftc,     // [B, 8]
    float4* __restrict__ out)        // [B, 16, 512, 512] / 4
{
    __shared__ float4 vtab[240];     // [wf][dh+7][par] : wf*30 + dh7*2 + par
    const int tid = threadIdx.x;
    const int blk = blockIdx.x;
    const int tp = blk & 7;
    const int tf = (blk >> 3) & 7;
    const int nh = (blk >> 6) & 15;
    const int b  = blk >> 10;

    const int t_f =  __ldg(ftc + b * 8 + tf);
    const int t_p = -__ldg(ptc + b * 8 + tp);
    const float* __restrict__ src = g_rpt + nh * NROWP + (t_f + t_p) * 225;

    if (tid < 240) {
        const int wf  = tid / 30;
        const int rem = tid - wf * 30;
        const int dh7 = rem >> 1;
        const int par = rem & 1;                       // wp0 = par*4
        const int si  = dh7 * 15 + wf - par * 4 + 7;   // in [3, 224]
        vtab[tid] = make_float4(__ldg(src + si),     __ldg(src + si - 1),
                                __ldg(src + si - 2), __ldg(src + si - 3));
    }
    __syncthreads();

    const int c4    = tid & 15;
    const int fhw0  = tid >> 4;            // 0..15
    const int wf    = fhw0 & 7;
    const int b0    = fhw0 >> 3;           // 0 or 1
    const int hp    = c4 >> 1;
    const int par   = c4 & 1;
    const int base0 = wf * 30 + (b0 - hp + 7) * 2 + par;   // k=0 index

    float4* __restrict__ p =
        out + ((((b * NHEAD + nh) * 512 + tf * 64) * 512 + tp * 64) >> 2)
            + fhw0 * 128 + c4;

    #pragma unroll
    for (int k = 0; k < 4; k++) {
        __stcs(p, vtab[base0 + 4 * k]);    // hf = b0 + 2k, always <= 7
        p += 2048;                          // fhw += 16
    }
}

// ---------------------------------------------------------------------------
// Launch. Input order: ptc, ftc, W1, b1, W2, rct, rpi_table (unused).
// ---------------------------------------------------------------------------
extern "C" void kernel_launch(void* const* d_in, const int* in_sizes, int n_in,
                              void* d_out, int out_size)
{
    const int*   ptc = (const int*)  d_in[0];
    const int*   ftc = (const int*)  d_in[1];
    const float* W1  = (const float*)d_in[2];
    const float* b1  = (const float*)d_in[3];
    const float* W2  = (const float*)d_in[4];
    const float* rct = (const float*)d_in[5];

    // 350 blocks x 64 rows = 22400 (NROWP); rows >= NROW are never read.
    mlp_kernel<<<NROWP / 64, 128>>>(rct, W1, b1, W2);

    // 8192 blocks: one per (b, nh, tf, tp) 64x64 tile
    gather_kernel<<<8 * NHEAD * 8 * 8, 256>>>(ptc, ftc, (float4*)d_out);
}